// round 15
// baseline (speedup 1.0000x reference)
#include <cuda_runtime.h>
#include <cuda_fp16.h>
#include <math.h>

#define N_NODES 50000
#define N_EDGES 800000
#define F 64
#define E_TOT (N_EDGES + N_NODES)
#define NEG_ATT 0.2f
#define NEG_ACT 0.01f
#define GEMM_ROWS 64
#define GEMM_GRID ((N_NODES + GEMM_ROWS - 1) / GEMM_ROWS)   // 782
#define EDGE_GRID ((E_TOT + 255) / 256)                     // 3321
#define SCAN_BLKS 49   // 49 * 1024 >= 50000; all co-resident

#define XT_PAD 66      // s_xT row stride (8B units): 528B, 16B-aligned

// -------- scratch (device globals; referenced ONLY inside kernels) --------
__device__ __align__(16) __half g_hh [N_NODES * F];   // fp16 h (aggregation)
__device__ __align__(16) float  g_x1 [N_NODES * F];
__device__ float g_as [N_NODES];
__device__ float g_ad [N_NODES];
__device__ int   g_cnt[N_NODES];        // zeroed by scan kernel each launch
__device__ int   g_cur[N_NODES];
__device__ int   g_rowstart[N_NODES + 1];
__device__ int   g_csrc[E_TOT];
__device__ int   g_btot[SCAN_BLKS];     // block totals double as ready flags

// -------- packed f32x2 helpers --------
__device__ __forceinline__ unsigned long long pack2(float lo, float hi) {
    unsigned long long r;
    asm("mov.b64 %0, {%1, %2};" : "=l"(r) : "f"(lo), "f"(hi));
    return r;
}
__device__ __forceinline__ void unpack2(unsigned long long v, float& lo, float& hi) {
    asm("mov.b64 {%0, %1}, %2;" : "=f"(lo), "=f"(hi) : "l"(v));
}
__device__ __forceinline__ unsigned long long fma2(unsigned long long a,
                                                   unsigned long long b,
                                                   unsigned long long c) {
    unsigned long long d;
    asm("fma.rn.f32x2 %0, %1, %2, %3;" : "=l"(d) : "l"(a), "l"(b), "l"(c));
    return d;
}

// -------- fp16 row load: 8B per lane -> 4 floats --------
__device__ __forceinline__ float4 ldh4(const __half* row, int hl) {
    uint2 raw = ((const uint2*)row)[hl];           // LDG.64
    __half2 a = *reinterpret_cast<__half2*>(&raw.x);
    __half2 b = *reinterpret_cast<__half2*>(&raw.y);
    float2 fa = __half22float2(a);
    float2 fb = __half22float2(b);
    return make_float4(fa.x, fa.y, fb.x, fb.y);
}

// ---- gemm+alpha body: 4 rows x 4 cols per thread, f32x2 pipe --------------
__device__ __forceinline__ void gemm_alpha_body(const float* __restrict__ xin,
                                                const float* __restrict__ W,
                                                const float* __restrict__ a_s,
                                                const float* __restrict__ a_d,
                                                int blk, int tid) {
    __shared__ unsigned long long s_w[F][32];           // 16 KB
    __shared__ unsigned long long s_xT[F][XT_PAD];      // 33 KB

    const int tx = tid & 15;
    const int ry = tid >> 4;
    const int row0 = blk * GEMM_ROWS;

    for (int i = tid; i < F * 32; i += 256) {
        float2 w2 = ((const float2*)W)[i];
        s_w[i >> 5][i & 31] = pack2(w2.x, w2.y);
    }
    for (int i = tid; i < GEMM_ROWS * F; i += 256) {
        int r = i >> 6, k = i & 63;
        int row = row0 + r;
        float xv = (row < N_NODES) ? xin[row * F + k] : 0.0f;
        s_xT[k][r] = pack2(xv, xv);
    }
    __syncthreads();

    const int r0 = ry * 4;
    unsigned long long a00 = 0, a01 = 0, a10 = 0, a11 = 0;
    unsigned long long a20 = 0, a21 = 0, a30 = 0, a31 = 0;
#pragma unroll
    for (int k = 0; k < F; k++) {
        ulonglong2 w  = *(const ulonglong2*)&s_w[k][2 * tx];
        ulonglong2 xa = *(const ulonglong2*)&s_xT[k][r0];
        ulonglong2 xb = *(const ulonglong2*)&s_xT[k][r0 + 2];
        a00 = fma2(xa.x, w.x, a00);  a01 = fma2(xa.x, w.y, a01);
        a10 = fma2(xa.y, w.x, a10);  a11 = fma2(xa.y, w.y, a11);
        a20 = fma2(xb.x, w.x, a20);  a21 = fma2(xb.x, w.y, a21);
        a30 = fma2(xb.y, w.x, a30);  a31 = fma2(xb.y, w.y, a31);
    }

    const float4 as4 = ((const float4*)a_s)[tx];
    const float4 ad4 = ((const float4*)a_d)[tx];
    unsigned long long p0[4] = {a00, a10, a20, a30};
    unsigned long long p1[4] = {a01, a11, a21, a31};
#pragma unroll
    for (int j = 0; j < 4; j++) {
        int row = row0 + r0 + j;
        float c0, c1, c2, c3;
        unpack2(p0[j], c0, c1);
        unpack2(p1[j], c2, c3);
        if (row < N_NODES) {
            __half2 pa = __floats2half2_rn(c0, c1);
            __half2 pb = __floats2half2_rn(c2, c3);
            __half2* hp = (__half2*)(g_hh + (size_t)row * F);
            hp[2 * tx]     = pa;
            hp[2 * tx + 1] = pb;
        }
        float ps = c0 * as4.x + c1 * as4.y + c2 * as4.z + c3 * as4.w;
        float pd = c0 * ad4.x + c1 * ad4.y + c2 * ad4.z + c3 * ad4.w;
#pragma unroll
        for (int o = 8; o > 0; o >>= 1) {
            ps += __shfl_down_sync(0xffffffffu, ps, o, 16);
            pd += __shfl_down_sync(0xffffffffu, pd, o, 16);
        }
        if (tx == 0 && row < N_NODES) { g_as[row] = ps; g_ad[row] = pd; }
    }
}

// ---- fused: blocks [0,GEMM_GRID) run layer-0 gemm+alpha; rest run hist ----
__global__ void hist_gemm_kernel(const int* __restrict__ ei,
                                 const float* __restrict__ x,
                                 const float* __restrict__ W,
                                 const float* __restrict__ a_s,
                                 const float* __restrict__ a_d) {
    const int tid = threadIdx.x;
    if (blockIdx.x < GEMM_GRID) {
        gemm_alpha_body(x, W, a_s, a_d, blockIdx.x, tid);
    } else {
        int e = (blockIdx.x - GEMM_GRID) * 256 + tid;
        if (e < E_TOT) {
            int dst = (e < N_EDGES) ? ei[N_EDGES + e] : (e - N_EDGES);
            atomicAdd(&g_cnt[dst], 1);
        }
    }
}

// ---- standalone gemm+alpha (layer 1) ----
__global__ void gemm_alpha_kernel(const float* __restrict__ W,
                                  const float* __restrict__ a_s,
                                  const float* __restrict__ a_d) {
    gemm_alpha_body(g_x1, W, a_s, a_d, blockIdx.x, threadIdx.x);
}

// ---- single-launch scan with decoupled lookback ----
__global__ void scan_kernel() {
    const int tid = threadIdx.x;
    const int lane = tid & 31, wid = tid >> 5;
    __shared__ int wsum[32];
    __shared__ int s_off;

    int i = blockIdx.x * 1024 + tid;
    int v = (i < N_NODES) ? g_cnt[i] : 0;
    int incl = v;
#pragma unroll
    for (int o = 1; o < 32; o <<= 1) {
        int t = __shfl_up_sync(0xffffffffu, incl, o);
        if (lane >= o) incl += t;
    }
    if (lane == 31) wsum[wid] = incl;
    __syncthreads();
    if (wid == 0) {
        int w = wsum[lane];
#pragma unroll
        for (int o = 1; o < 32; o <<= 1) {
            int t = __shfl_up_sync(0xffffffffu, w, o);
            if (lane >= o) w += t;
        }
        wsum[lane] = w;
    }
    __syncthreads();
    int loc_incl = incl + (wid > 0 ? wsum[wid - 1] : 0);

    if (tid == 1023)
        *((volatile int*)&g_btot[blockIdx.x]) = loc_incl;

    if (wid == 0) {
        int sum = 0;
        for (int j = lane; j < blockIdx.x; j += 32) {
            int t;
            do { t = *((volatile int*)&g_btot[j]); } while (t == 0);
            sum += t;
        }
#pragma unroll
        for (int o = 16; o > 0; o >>= 1) sum += __shfl_xor_sync(0xffffffffu, sum, o);
        if (lane == 0) s_off = sum;
    }
    __syncthreads();

    if (i < N_NODES) {
        int rs = loc_incl + s_off;
        g_rowstart[i + 1] = rs;
        g_cur[i] = rs - v;
        g_cnt[i] = 0;
        if (i == 0) g_rowstart[0] = 0;
    }
}

__global__ void scatter_kernel(const int* __restrict__ ei) {
    int e = blockIdx.x * blockDim.x + threadIdx.x;
    if (e >= E_TOT) return;
    int src, dst;
    if (e < N_EDGES) { src = ei[e]; dst = ei[N_EDGES + e]; }
    else             { src = dst = e - N_EDGES; }
    int pos = atomicAdd(&g_cur[dst], 1);
    g_csrc[pos] = src;
}

// ========== gather: warp per dst node, 8 edges in flight, fp16 h rows =======
__global__ void gather_kernel(const float* __restrict__ b,
                              const float* __restrict__ xres,
                              float* __restrict__ outp,
                              int final_layer) {
    int gt = blockIdx.x * blockDim.x + threadIdx.x;
    int node = gt >> 5;
    int lane = gt & 31;
    if (node >= N_NODES) return;

    const int half = lane >> 4;
    const int hl   = lane & 15;

    int beg = g_rowstart[node];
    int end = g_rowstart[node + 1];
    float ad_n = g_ad[node];

    float4 accA = make_float4(0.0f, 0.0f, 0.0f, 0.0f);
    float4 accB = make_float4(0.0f, 0.0f, 0.0f, 0.0f);
    float zsum = 0.0f;

    for (int c = beg; c < end; c += 32) {
        int j = c + lane;
        int s = 0;
        float ex = 0.0f;
        if (j < end) {
            s = g_csrc[j];
            float v = g_as[s] + ad_n;
            v = v > 0.0f ? v : NEG_ATT * v;
            ex = __expf(v);
            zsum += ex;
        }
        int cnt = min(32, end - c);
        int T = (cnt + 7) >> 3;          // 8 edges per warp-iteration
        for (int t = 0; t < T; t++) {
            int kb = (t << 3) + (half << 2);
            int k0 = kb, k1 = kb + 1, k2 = kb + 2, k3 = kb + 3;
            int ks0 = k0 < cnt ? k0 : cnt - 1;
            int ks1 = k1 < cnt ? k1 : cnt - 1;
            int ks2 = k2 < cnt ? k2 : cnt - 1;
            int ks3 = k3 < cnt ? k3 : cnt - 1;
            int   s0 = __shfl_sync(0xffffffffu, s,  ks0);
            int   s1 = __shfl_sync(0xffffffffu, s,  ks1);
            int   s2 = __shfl_sync(0xffffffffu, s,  ks2);
            int   s3 = __shfl_sync(0xffffffffu, s,  ks3);
            float e0 = __shfl_sync(0xffffffffu, ex, ks0);
            float e1 = __shfl_sync(0xffffffffu, ex, ks1);
            float e2 = __shfl_sync(0xffffffffu, ex, ks2);
            float e3 = __shfl_sync(0xffffffffu, ex, ks3);
            if (k0 >= cnt) e0 = 0.0f;
            if (k1 >= cnt) e1 = 0.0f;
            if (k2 >= cnt) e2 = 0.0f;
            if (k3 >= cnt) e3 = 0.0f;
            float4 h0 = ldh4(g_hh + (size_t)s0 * F, hl);
            float4 h1 = ldh4(g_hh + (size_t)s1 * F, hl);
            float4 h2 = ldh4(g_hh + (size_t)s2 * F, hl);
            float4 h3 = ldh4(g_hh + (size_t)s3 * F, hl);
            accA.x = fmaf(h0.x, e0, accA.x);
            accA.y = fmaf(h0.y, e0, accA.y);
            accA.z = fmaf(h0.z, e0, accA.z);
            accA.w = fmaf(h0.w, e0, accA.w);
            accB.x = fmaf(h1.x, e1, accB.x);
            accB.y = fmaf(h1.y, e1, accB.y);
            accB.z = fmaf(h1.z, e1, accB.z);
            accB.w = fmaf(h1.w, e1, accB.w);
            accA.x = fmaf(h2.x, e2, accA.x);
            accA.y = fmaf(h2.y, e2, accA.y);
            accA.z = fmaf(h2.z, e2, accA.z);
            accA.w = fmaf(h2.w, e2, accA.w);
            accB.x = fmaf(h3.x, e3, accB.x);
            accB.y = fmaf(h3.y, e3, accB.y);
            accB.z = fmaf(h3.z, e3, accB.z);
            accB.w = fmaf(h3.w, e3, accB.w);
        }
    }
    float4 acc = make_float4(accA.x + accB.x, accA.y + accB.y,
                             accA.z + accB.z, accA.w + accB.w);
    acc.x += __shfl_down_sync(0xffffffffu, acc.x, 16);
    acc.y += __shfl_down_sync(0xffffffffu, acc.y, 16);
    acc.z += __shfl_down_sync(0xffffffffu, acc.z, 16);
    acc.w += __shfl_down_sync(0xffffffffu, acc.w, 16);
#pragma unroll
    for (int o = 16; o > 0; o >>= 1) zsum += __shfl_xor_sync(0xffffffffu, zsum, o);

    if (half == 0) {
        float inv = 1.0f / (zsum + 1e-16f);
        float4 bv = ((const float4*)b)[hl];
        float vx = fmaf(acc.x, inv, bv.x);
        float vy = fmaf(acc.y, inv, bv.y);
        float vz = fmaf(acc.z, inv, bv.z);
        float vw = fmaf(acc.w, inv, bv.w);
        vx = vx > 0.0f ? vx : NEG_ACT * vx;
        vy = vy > 0.0f ? vy : NEG_ACT * vy;
        vz = vz > 0.0f ? vz : NEG_ACT * vz;
        vw = vw > 0.0f ? vw : NEG_ACT * vw;
        if (final_layer) {
            float4 xr = ((const float4*)(xres + (size_t)node * F))[hl];
            vx += xr.x; vy += xr.y; vz += xr.z; vw += xr.w;
            ((float4*)(outp + (size_t)node * F))[hl] = make_float4(vx, vy, vz, vw);
        } else {
            ((float4*)(g_x1 + (size_t)node * F))[hl] = make_float4(vx, vy, vz, vw);
        }
    }
}

extern "C" void kernel_launch(void* const* d_in, const int* in_sizes, int n_in,
                              void* d_out, int out_size) {
    const float* x    = (const float*)d_in[0];
    const int*   ei   = (const int*)d_in[1];
    const float* W0   = (const float*)d_in[2];
    const float* as0  = (const float*)d_in[3];
    const float* ad0  = (const float*)d_in[4];
    const float* b0   = (const float*)d_in[5];
    const float* W1   = (const float*)d_in[6];
    const float* as1  = (const float*)d_in[7];
    const float* ad1  = (const float*)d_in[8];
    const float* b1   = (const float*)d_in[9];
    float*       out  = (float*)d_out;

    const int TB = 256;
    const int gthGrid = (N_NODES * 32 + TB - 1) / TB;

    // ---- CSR build overlapped with layer-0 gemm+alpha ----
    hist_gemm_kernel<<<GEMM_GRID + EDGE_GRID, TB>>>(ei, x, W0, as0, ad0);
    scan_kernel<<<SCAN_BLKS, 1024>>>();
    scatter_kernel<<<EDGE_GRID, TB>>>(ei);

    // ---- layer 0 aggregate (writes g_x1 internally) ----
    gather_kernel<<<gthGrid, TB>>>(b0, x, out, 0);

    // ---- layer 1 ----
    gemm_alpha_kernel<<<GEMM_GRID, TB>>>(W1, as1, ad1);
    gather_kernel<<<gthGrid, TB>>>(b1, x, out, 1);
}